// round 7
// baseline (speedup 1.0000x reference)
#include <cuda_runtime.h>
#include <math.h>

#define NB 8
#define NH 512
#define NW 512
#define NP 32
#define HWC (NH*NW)
#define EPSF 1e-8f
#define INV2BW2 50.0f
#define NSEG 32
#define SEGROWS 16
#define PSPLIT 8
#define SDSTRIDE 544        /* >= 512 + 32 skew: max skewed index 511+31=542 */

/* ---------------- scratch (device globals) ---------------- */
__device__ float g_ex[NB*NP*NW];
__device__ float g_ey[NB*NP*NH];
__device__ float g_sx[NB*NP];
__device__ float g_sy[NB*NP];
__device__ float g_psum_part[NB*PSPLIT];
__device__ float g_diff[NB*HWC];        /* 8 MB */
__device__ float g_colseg[NB*NSEG*NW];  /* seg column sums -> exclusive carries */
__device__ float g_part_kl[NB*NSEG];
__device__ float g_part_emdw[NB*NSEG];
__device__ float g_part_emdh[NB*NSEG];
__device__ float g_amax_pval[NB*NSEG];
__device__ int   g_amax_pidx[NB*NSEG];
__device__ float g_amax_tval[NB*NSEG];
__device__ int   g_amax_tidx[NB*NSEG];

/* fast ln(x) for positive normal x: FMA-pipe only (no MUFU).
   ln(x) = e*ln2 + ln(m), m in [2/3, 4/3), t = m-1 in [-1/3, 1/3],
   Taylor to t^11: abs err <= (1/3)^12/12 ~ 1.6e-7 */
__device__ __forceinline__ float fast_ln(float x) {
    int bi = __float_as_int(x);
    int e = (bi >> 23) - 127;
    float m = __int_as_float((bi & 0x007FFFFF) | 0x3F800000);  /* [1,2) */
    if (m > 1.33333333f) { m *= 0.5f; e += 1; }
    float t = m - 1.0f;
    float p = fmaf(t, 1.0f/11.0f, -1.0f/10.0f);
    p = fmaf(t, p,  1.0f/9.0f);
    p = fmaf(t, p, -0.125f);
    p = fmaf(t, p,  1.0f/7.0f);
    p = fmaf(t, p, -1.0f/6.0f);
    p = fmaf(t, p,  0.2f);
    p = fmaf(t, p, -0.25f);
    p = fmaf(t, p,  1.0f/3.0f);
    p = fmaf(t, p, -0.5f);
    p = fmaf(t, p,  1.0f);
    return fmaf((float)e, 0.693147181f, t * p);
}

/* ===== K1: fused (a) gaussian factors + 1-D sums, (b) pred partial sums ===== */
__global__ __launch_bounds__(512) void k_prep(const float* __restrict__ pts,
                                              const float4* __restrict__ pred4) {
    int blk = blockIdx.x;
    int t = threadIdx.x, lane = t & 31, wid = t >> 5;
    __shared__ float sred[16];

    if (blk < NB*NP) {
        int bn = blk;
        float px = pts[bn*2 + 0];
        float py = pts[bn*2 + 1];
        float c  = (float)t * (1.0f/511.0f);
        float dx = c - px, dy = c - py;
        float ex = __expf(-dx*dx*INV2BW2);
        float ey = __expf(-dy*dy*INV2BW2);
        g_ex[bn*NW + t] = ex;
        g_ey[bn*NH + t] = ey;

        float v = ex;
#pragma unroll
        for (int off = 16; off; off >>= 1) v += __shfl_xor_sync(~0u, v, off);
        if (lane == 0) sred[wid] = v;
        __syncthreads();
        if (t == 0) { float s = 0.f;
#pragma unroll
            for (int j = 0; j < 16; j++) s += sred[j];
            g_sx[bn] = s; }
        __syncthreads();
        v = ey;
#pragma unroll
        for (int off = 16; off; off >>= 1) v += __shfl_xor_sync(~0u, v, off);
        if (lane == 0) sred[wid] = v;
        __syncthreads();
        if (t == 0) { float s = 0.f;
#pragma unroll
            for (int j = 0; j < 16; j++) s += sred[j];
            g_sy[bn] = s; }
    } else {
        int part = blk - NB*NP;           /* 0..63 */
        const float4* p = pred4 + part * 8192;
        float s = 0.f;
#pragma unroll 4
        for (int i = 0; i < 16; i++) {
            float4 v = p[t + i*512];
            s += (v.x + v.y) + (v.z + v.w);
        }
#pragma unroll
        for (int off = 16; off; off >>= 1) s += __shfl_xor_sync(~0u, s, off);
        if (lane == 0) sred[wid] = s;
        __syncthreads();
        if (t == 0) { float a = 0.f;
#pragma unroll
            for (int j = 0; j < 16; j++) a += sred[j];
            g_psum_part[part] = a; }
    }
}

/* ===== K2: fused density + KL(poly-log) + diff + EMD-W scan + argmax;
         normalizers computed inline by warp 0 ===== */
__global__ __launch_bounds__(512, 2) void k_main(const float* __restrict__ pred,
                                                 const float* __restrict__ mask) {
    int blk = blockIdx.x;                 /* b*NSEG+seg, 256 blocks */
    int b = blk >> 5, seg = blk & 31;
    int w = threadIdx.x, lane = w & 31, wid = w >> 5;

    __shared__ float sEy[SEGROWS*NP];
    __shared__ float sD[SEGROWS*SDSTRIDE];
    __shared__ float sred[16];
    __shared__ int   sidx[16];
    __shared__ float sNorm[3];            /* m, invSp, invSt */

    sEy[(w >> 5)*NP + (w & 31)] = g_ey[(b*NP + (w & 31))*NH + seg*SEGROWS + (w >> 5)];

    if (wid == 0) {                       /* inline normalizers */
        float ps = (lane < PSPLIT) ? g_psum_part[b*PSPLIT + lane] : 0.f;
        float ts = g_sx[b*NP + lane] * g_sy[b*NP + lane];
#pragma unroll
        for (int off = 16; off; off >>= 1) {
            ps += __shfl_xor_sync(~0u, ps, off);
            ts += __shfl_xor_sync(~0u, ts, off);
        }
        if (lane == 0) {
            float m = mask[b];
            sNorm[0] = m;
            sNorm[1] = 1.0f / (m*ps + (float)HWC*EPSF);
            sNorm[2] = 1.0f / (m*ts + (float)HWC*EPSF);
        }
    }

    float rex[NP];
#pragma unroll
    for (int n = 0; n < NP; n++) rex[n] = g_ex[(b*NP + n)*NW + w];
    __syncthreads();

    float m     = sNorm[0];
    float invSp = sNorm[1];
    float invSt = sNorm[2];

    float klacc = 0.f, ccol = 0.f;
    float apv = -1e30f, atv = -1e30f;
    int   api = 0, ati = 0;
    int rowbase = (b*NH + seg*SEGROWS)*NW + w;
    int skw = w + (w >> 4);

#pragma unroll 2
    for (int r = 0; r < SEGROWS; r++) {
        float p = __ldg(&pred[rowbase + r*NW]);
        float acc = 0.f;
#pragma unroll
        for (int n = 0; n < NP; n++) acc = fmaf(sEy[r*NP + n], rex[n], acc);
        float pm = p * m, tm = acc * m;
        float pn = (pm + EPSF) * invSp;
        float tn = (tm + EPSF) * invSt;
        float d  = pn - tn;
        g_diff[rowbase + r*NW] = d;
        sD[r*SDSTRIDE + skw] = d;
        klacc = fmaf(tn, fast_ln(tn) - fast_ln(pn + EPSF), klacc);
        ccol += d;
        int fid = (seg*SEGROWS + r)*NW + w;
        if (pm > apv) { apv = pm; api = fid; }
        if (tm > atv) { atv = tm; ati = fid; }
    }
    g_colseg[blk*NW + w] = ccol;
    __syncthreads();

    /* EMD-W: warp wid scans row wid; lane owns 16 contiguous elems */
    float ewacc = 0.f;
    {
        float vals[16];
        int base = wid*SDSTRIDE + lane*17;     /* skew(16*lane+i) = 17*lane+i */
        float s = 0.f;
#pragma unroll
        for (int i = 0; i < 16; i++) { vals[i] = sD[base + i]; s += vals[i]; }
        float incl = s;
#pragma unroll
        for (int off = 1; off < 32; off <<= 1) {
            float u = __shfl_up_sync(~0u, incl, off);
            if (lane >= off) incl += u;
        }
        float run = incl - s;
#pragma unroll
        for (int i = 0; i < 16; i++) { run += vals[i]; ewacc += fabsf(run); }
    }

    /* block reductions */
    float v = klacc;
#pragma unroll
    for (int off = 16; off; off >>= 1) v += __shfl_xor_sync(~0u, v, off);
    if (lane == 0) sred[wid] = v;
    __syncthreads();
    if (w == 0) { float s = 0.f;
#pragma unroll
        for (int j = 0; j < 16; j++) s += sred[j];
        g_part_kl[blk] = s; }
    __syncthreads();

    v = ewacc;
#pragma unroll
    for (int off = 16; off; off >>= 1) v += __shfl_xor_sync(~0u, v, off);
    if (lane == 0) sred[wid] = v;
    __syncthreads();
    if (w == 0) { float s = 0.f;
#pragma unroll
        for (int j = 0; j < 16; j++) s += sred[j];
        g_part_emdw[blk] = s; }
    __syncthreads();

    /* argmax pred (val desc, idx asc) */
    float av = apv; int ai = api;
#pragma unroll
    for (int off = 16; off; off >>= 1) {
        float ov = __shfl_xor_sync(~0u, av, off);
        int   oi = __shfl_xor_sync(~0u, ai, off);
        if (ov > av || (ov == av && oi < ai)) { av = ov; ai = oi; }
    }
    if (lane == 0) { sred[wid] = av; sidx[wid] = ai; }
    __syncthreads();
    if (w == 0) {
        float bv = sred[0]; int bi = sidx[0];
#pragma unroll
        for (int j = 1; j < 16; j++)
            if (sred[j] > bv || (sred[j] == bv && sidx[j] < bi)) { bv = sred[j]; bi = sidx[j]; }
        g_amax_pval[blk] = bv; g_amax_pidx[blk] = bi;
    }
    __syncthreads();

    /* argmax targ */
    av = atv; ai = ati;
#pragma unroll
    for (int off = 16; off; off >>= 1) {
        float ov = __shfl_xor_sync(~0u, av, off);
        int   oi = __shfl_xor_sync(~0u, ai, off);
        if (ov > av || (ov == av && oi < ai)) { av = ov; ai = oi; }
    }
    if (lane == 0) { sred[wid] = av; sidx[wid] = ai; }
    __syncthreads();
    if (w == 0) {
        float bv = sred[0]; int bi = sidx[0];
#pragma unroll
        for (int j = 1; j < 16; j++)
            if (sred[j] > bv || (sred[j] == bv && sidx[j] < bi)) { bv = sred[j]; bi = sidx[j]; }
        g_amax_tval[blk] = bv; g_amax_tidx[blk] = bi;
    }
}

/* ===== K3: colseg -> exclusive carries. 32 INDEPENDENT loads/thread,
         register prefix (no dependent global chain). ===== */
__global__ __launch_bounds__(512) void k_carry() {
    int b = blockIdx.x;                   /* 8 blocks */
    int w = threadIdx.x;
    float v[NSEG];
#pragma unroll
    for (int s = 0; s < NSEG; s++) v[s] = g_colseg[(b*NSEG + s)*NW + w];
    float run = 0.f;
#pragma unroll
    for (int s = 0; s < NSEG; s++) {
        g_colseg[(b*NSEG + s)*NW + w] = run;
        run += v[s];
    }
}

/* ===== K4: EMD-along-H (single carry load + local column scan) ===== */
__global__ __launch_bounds__(512) void k_emdh() {
    int blk = blockIdx.x;                 /* b*NSEG+seg */
    int b = blk >> 5, seg = blk & 31;
    int w = threadIdx.x, lane = w & 31, wid = w >> 5;

    float c = g_colseg[blk*NW + w];       /* exclusive carry */
    const float* dptr = &g_diff[(b*NH + seg*SEGROWS)*NW + w];
    float acc = 0.f;
#pragma unroll
    for (int r = 0; r < SEGROWS; r++) { c += dptr[r*NW]; acc += fabsf(c); }

#pragma unroll
    for (int off = 16; off; off >>= 1) acc += __shfl_xor_sync(~0u, acc, off);
    __shared__ float sred[16];
    if (lane == 0) sred[wid] = acc;
    __syncthreads();
    if (w == 0) { float s = 0.f;
#pragma unroll
        for (int j = 0; j < 16; j++) s += sred[j];
        g_part_emdh[blk] = s; }
}

/* ===== K5: finalize ===== */
__global__ __launch_bounds__(256) void k_final(float* __restrict__ out, int out_size) {
    int t = threadIdx.x;                  /* 256 */
    int lane = t & 31, wid = t >> 5;
    __shared__ float sred[8];
    __shared__ float res3[3];
    __shared__ float ppx[NB], ppy[NB], tpx[NB], tpy[NB];

    const float* srcs[3] = { g_part_kl, g_part_emdw, g_part_emdh };
    for (int k = 0; k < 3; k++) {
        float v = srcs[k][t];
#pragma unroll
        for (int off = 16; off; off >>= 1) v += __shfl_xor_sync(~0u, v, off);
        if (lane == 0) sred[wid] = v;
        __syncthreads();
        if (t == 0) { float s = 0.f;
#pragma unroll
            for (int j = 0; j < 8; j++) s += sred[j];
            res3[k] = s; }
        __syncthreads();
    }

    {
        float av = g_amax_pval[t]; int ai = g_amax_pidx[t];
#pragma unroll
        for (int off = 16; off; off >>= 1) {
            float ov = __shfl_xor_sync(~0u, av, off);
            int   oi = __shfl_xor_sync(~0u, ai, off);
            if (ov > av || (ov == av && oi < ai)) { av = ov; ai = oi; }
        }
        if (lane == 0) {
            ppy[wid] = (float)(ai / NW) * (1.0f/511.0f);
            ppx[wid] = (float)(ai % NW) * (1.0f/511.0f);
        }
        av = g_amax_tval[t]; ai = g_amax_tidx[t];
#pragma unroll
        for (int off = 16; off; off >>= 1) {
            float ov = __shfl_xor_sync(~0u, av, off);
            int   oi = __shfl_xor_sync(~0u, ai, off);
            if (ov > av || (ov == av && oi < ai)) { av = ov; ai = oi; }
        }
        if (lane == 0) {
            tpy[wid] = (float)(ai / NW) * (1.0f/511.0f);
            tpx[wid] = (float)(ai % NW) * (1.0f/511.0f);
        }
    }
    __syncthreads();

    if (t == 0) {
        float loss = res3[0] * (1.0f/(float)NB);
        float emd  = (res3[1] + res3[2]) * (0.5f / ((float)NB * (float)HWC));
        int cnt = 0;
        for (int b = 0; b < NB; b++) {
            float dx = ppx[b]-tpx[b], dy = ppy[b]-tpy[b];
            if (sqrtf(dx*dx + dy*dy) < 0.1f) cnt++;
        }
        float acc = (float)cnt * (1.0f/(float)NB);
        if (out_size > 0) out[0] = loss;
        if (out_size > 1) out[1] = emd;
        if (out_size > 2) out[2] = acc;
    }
}

extern "C" void kernel_launch(void* const* d_in, const int* in_sizes, int n_in,
                              void* d_out, int out_size) {
    const float* pred = (const float*)d_in[0];   /* [8,512,512] */
    const float* pts  = (const float*)d_in[1];   /* [8,32,2]    */
    const float* mask = (const float*)d_in[2];   /* [8]         */
    float* out = (float*)d_out;

    k_prep<<<NB*NP + NB*PSPLIT, 512>>>(pts, (const float4*)pred);
    k_main<<<NB*NSEG, 512>>>(pred, mask);
    k_carry<<<NB, 512>>>();
    k_emdh<<<NB*NSEG, 512>>>();
    k_final<<<1, 256>>>(out, out_size);
}